// round 9
// baseline (speedup 1.0000x reference)
#include <cuda_runtime.h>
#include <cuda_bf16.h>
#include <cuda_fp16.h>
#include <math.h>
#include <stdint.h>

#define Kc 65536
#define Dc 256
#define Oc 256
#define Bc 1024
#define TOPK 32
#define NCAND 48
#define NCAP 96
#define NTILES 512
#define TCAP 128
#define TWOD 512
#define SHIFT_FULL 491.25f
#define SHIFT_UNI  363.25f
#define HALF_D_LOG2PI 235.2482645f   // 0.5 * 256 * ln(2*pi)
#define QSCALE (127.0f / 6.0f)
#define QSC2   (36.0f / 16129.0f)    // (6/127)^2

// ---------------- device scratch ----------------
__device__ __nv_bfloat16 g_xb[(size_t)Bc * TWOD];        // 1 MB  [x | -0.5x^2] (fallback)
__device__ __nv_bfloat16 g_wb[(size_t)Kc * TWOD];        // 64 MB [m*iv | iv]   (fallback)
__device__ signed char   g_xq[(size_t)Bc * Dc];          // 256 KB int8 x
__device__ signed char   g_wq[(size_t)Kc * Dc];          // 16 MB int8 mean
__device__ float         g_bias[Kc];
__device__ __half        g_lh[(size_t)Bc * Kc];          // 128 MB shifted logits
__device__ float         g_tmax[(size_t)Bc * NTILES];    // 2 MB per-row per-tile max
__device__ int           g_flag;                          // 1 => stddev == 1 everywhere

__device__ __forceinline__ float neg_inf() { return __int_as_float(0xff800000); }

__device__ __forceinline__ uint32_t smem_u32(const void* p) {
    uint32_t a;
    asm("{ .reg .u64 t; cvta.to.shared.u64 t, %1; cvt.u32.u64 %0, t; }" : "=r"(a) : "l"(p));
    return a;
}
__device__ __forceinline__ void cp_async16(uint32_t dst, const void* src) {
    asm volatile("cp.async.cg.shared.global [%0], [%1], 16;" :: "r"(dst), "l"(src));
}
#define CP_COMMIT() asm volatile("cp.async.commit_group;" ::: "memory")
#define CP_WAIT(n)  asm volatile("cp.async.wait_group %0;" :: "n"(n) : "memory")

#define LDSM_X4(r, addr) \
    asm volatile("ldmatrix.sync.aligned.m8n8.x4.shared.b16 {%0,%1,%2,%3}, [%4];" \
        : "=r"((r)[0]), "=r"((r)[1]), "=r"((r)[2]), "=r"((r)[3]) : "r"(addr))

__device__ __forceinline__ void mma16816(float* c, const uint32_t* a, uint32_t b0, uint32_t b1) {
    asm volatile("mma.sync.aligned.m16n8k16.row.col.f32.bf16.bf16.f32 "
        "{%0,%1,%2,%3}, {%4,%5,%6,%7}, {%8,%9}, {%0,%1,%2,%3};"
        : "+f"(c[0]), "+f"(c[1]), "+f"(c[2]), "+f"(c[3])
        : "r"(a[0]), "r"(a[1]), "r"(a[2]), "r"(a[3]), "r"(b0), "r"(b1));
}
__device__ __forceinline__ void mma16832_s8(int* c, const uint32_t* a, uint32_t b0, uint32_t b1) {
    asm volatile("mma.sync.aligned.m16n8k32.row.col.s32.s8.s8.s32 "
        "{%0,%1,%2,%3}, {%4,%5,%6,%7}, {%8,%9}, {%0,%1,%2,%3};"
        : "+r"(c[0]), "+r"(c[1]), "+r"(c[2]), "+r"(c[3])
        : "r"(a[0]), "r"(a[1]), "r"(a[2]), "r"(a[3]), "r"(b0), "r"(b1));
}

__device__ __forceinline__ signed char q6(float v) {
    int i = __float2int_rn(v * QSCALE);
    i = max(-127, min(127, i));
    return (signed char)i;
}

// both halves of a half2 word -> order-preserving 16-bit keys
__device__ __forceinline__ uint32_t key2(uint32_t h2) {
    uint32_t s = h2 & 0x80008000u;
    uint32_t m = 0x80008000u | ((s >> 15) * 0x7FFFu);
    return h2 ^ m;
}
__device__ __forceinline__ uint32_t fkey(float f) {
    uint32_t u = __float_as_uint(f);
    return (u & 0x80000000u) ? ~u : (u | 0x80000000u);
}

// ---------------- prep kernels ----------------
__global__ void prep_x_kernel(const float* __restrict__ x) {
    int b = blockIdx.x, d = threadIdx.x;
    float v = x[b * Dc + d];
    g_xb[(size_t)b * TWOD + d]      = __float2bfloat16(v);
    g_xb[(size_t)b * TWOD + Dc + d] = __float2bfloat16(-0.5f * v * v);
    g_xq[(size_t)b * Dc + d] = q6(v);
    if (b == 0 && d == 0) g_flag = 1;   // reset each launch (graph-replay safe)
}

// one block = 4 k rows; thread handles 4 elements
__global__ void __launch_bounds__(256) prep_w_kernel(const float* __restrict__ mean,
                                                     const float* __restrict__ stddev) {
    int k = blockIdx.x * 4 + (threadIdx.x >> 6);
    int e = (threadIdx.x & 63) * 4;
    float4 m4 = *(const float4*)&mean[(size_t)k * Dc + e];
    float4 s4 = *(const float4*)&stddev[(size_t)k * Dc + e];
    bool nonuni = (s4.x != 1.0f) | (s4.y != 1.0f) | (s4.z != 1.0f) | (s4.w != 1.0f);
    if (nonuni) g_flag = 0;

    char4 qv;
    qv.x = q6(m4.x); qv.y = q6(m4.y); qv.z = q6(m4.z); qv.w = q6(m4.w);
    *(char4*)&g_wq[(size_t)k * Dc + e] = qv;

    float ivx = 1.0f / (s4.x * s4.x), ivy = 1.0f / (s4.y * s4.y);
    float ivz = 1.0f / (s4.z * s4.z), ivw = 1.0f / (s4.w * s4.w);
    float part = -0.5f * (m4.x * m4.x * ivx + m4.y * m4.y * ivy +
                          m4.z * m4.z * ivz + m4.w * m4.w * ivw);
    if (nonuni)
        part -= logf(s4.x) + logf(s4.y) + logf(s4.z) + logf(s4.w);

    #pragma unroll
    for (int off = 16; off > 0; off >>= 1)
        part += __shfl_xor_sync(0xffffffffu, part, off);
    __shared__ float red[8];
    int warp = threadIdx.x >> 5;
    if ((threadIdx.x & 31) == 0) red[warp] = part;
    __syncthreads();
    if (threadIdx.x < 4)
        g_bias[blockIdx.x * 4 + threadIdx.x] =
            red[2 * threadIdx.x] + red[2 * threadIdx.x + 1] - HALF_D_LOG2PI;
}

// fallback only: bf16 packed weights (runs only when stddev != 1 somewhere)
__global__ void __launch_bounds__(512) prep_w_bf16_kernel(const float* __restrict__ mean,
                                                          const float* __restrict__ stddev) {
    if (g_flag) return;
    int k = blockIdx.x * 2 + (threadIdx.x >> 8);
    int d = threadIdx.x & 255;
    float s  = stddev[(size_t)k * Dc + d];
    float m  = mean[(size_t)k * Dc + d];
    float iv = 1.0f / (s * s);
    g_wb[(size_t)k * TWOD + d]      = __float2bfloat16(m * iv);
    g_wb[(size_t)k * TWOD + Dc + d] = __float2bfloat16(iv);
}

// ---------------- shared GEMM config ----------------
#define NSTAGE 4
#define ROWB   80
#define STAGE_BYTES (128 * ROWB * 2)   // A + B per stage = 20480
#define GEMM_SMEM (NSTAGE * STAGE_BYTES)

// ---------------- int8 GEMM (uniform-stddev fast path) ----------------
__device__ __forceinline__ void load_stage_i8(uint32_t sbase, int st, int m0, int n0, int k0, int tid) {
    uint32_t ab = sbase + st * STAGE_BYTES;
    uint32_t bb = ab + 128 * ROWB;
    #pragma unroll
    for (int i = 0; i < 2; i++) {
        int lin = tid + (i << 8);
        int row = lin >> 2, ch = lin & 3;
        cp_async16(ab + row * ROWB + ch * 16, g_xq + (size_t)(m0 + row) * Dc + k0 + ch * 16);
        cp_async16(bb + row * ROWB + ch * 16, g_wq + (size_t)(n0 + row) * Dc + k0 + ch * 16);
    }
    CP_COMMIT();
}

__global__ void __launch_bounds__(256, 2) gemm_i8_kernel() {
    if (!g_flag) return;
    extern __shared__ char smem[];
    __shared__ float smax[128][4];
    uint32_t sbase = smem_u32(smem);
    int tid = threadIdx.x, wid = tid >> 5, lane = tid & 31;
    int m0 = blockIdx.y * 128;
    int n0 = blockIdx.x * 128;
    int wm = wid >> 2, wn = wid & 3;

    int acc[4][4][4];
    #pragma unroll
    for (int mt = 0; mt < 4; mt++)
        #pragma unroll
        for (int nt = 0; nt < 4; nt++)
            #pragma unroll
            for (int q = 0; q < 4; q++) acc[mt][nt][q] = 0;

    load_stage_i8(sbase, 0, m0, n0, 0, tid);
    load_stage_i8(sbase, 1, m0, n0, 64, tid);
    load_stage_i8(sbase, 2, m0, n0, 128, tid);

    uint32_t a_row = (uint32_t)(wm * 64 + (lane & 15));
    uint32_t a_off = a_row * ROWB + ((lane >> 4) << 4);
    uint32_t b_row = (uint32_t)(wn * 32 + (lane & 7) + ((lane >> 4) << 3));
    uint32_t b_off = b_row * ROWB + (((lane >> 3) & 1) << 4);

    #pragma unroll 1
    for (int it = 0; it < 4; it++) {
        CP_WAIT(2);
        __syncthreads();
        if (it + 3 < 4) load_stage_i8(sbase, (it + 3) % NSTAGE, m0, n0, (it + 3) * 64, tid);
        else CP_COMMIT();

        int st = it % NSTAGE;
        uint32_t ab = sbase + st * STAGE_BYTES;
        uint32_t bb = ab + 128 * ROWB;

        #pragma unroll
        for (int ks = 0; ks < 2; ks++) {
            uint32_t afr[4][4];
            #pragma unroll
            for (int mt = 0; mt < 4; mt++)
                LDSM_X4(afr[mt], ab + a_off + mt * (16 * ROWB) + ks * 32);
            uint32_t bfr[2][4];
            #pragma unroll
            for (int np = 0; np < 2; np++)
                LDSM_X4(bfr[np], bb + b_off + np * (16 * ROWB) + ks * 32);
            #pragma unroll
            for (int mt = 0; mt < 4; mt++)
                #pragma unroll
                for (int nt = 0; nt < 4; nt++)
                    mma16832_s8(acc[mt][nt], afr[mt],
                                bfr[nt >> 1][(nt & 1) * 2], bfr[nt >> 1][(nt & 1) * 2 + 1]);
        }
    }
    CP_WAIT(0);

    const float NI = neg_inf();
    float rmA[4], rmB[4];
    #pragma unroll
    for (int mt = 0; mt < 4; mt++) { rmA[mt] = NI; rmB[mt] = NI; }

    #pragma unroll
    for (int nt = 0; nt < 4; nt++) {
        int col = n0 + wn * 32 + nt * 8 + (lane & 3) * 2;
        float2 bb2 = *(const float2*)&g_bias[col];
        float bx = bb2.x + SHIFT_UNI, by = bb2.y + SHIFT_UNI;
        #pragma unroll
        for (int mt = 0; mt < 4; mt++) {
            int row = m0 + wm * 64 + mt * 16 + (lane >> 2);
            float a0 = __int2float_rn(acc[mt][nt][0]) * QSC2 + bx;
            float a1 = __int2float_rn(acc[mt][nt][1]) * QSC2 + by;
            float a2 = __int2float_rn(acc[mt][nt][2]) * QSC2 + bx;
            float a3 = __int2float_rn(acc[mt][nt][3]) * QSC2 + by;
            rmA[mt] = fmaxf(rmA[mt], fmaxf(a0, a1));
            rmB[mt] = fmaxf(rmB[mt], fmaxf(a2, a3));
            *(__half2*)(g_lh + (size_t)row * Kc + col)       = __floats2half2_rn(a0, a1);
            *(__half2*)(g_lh + (size_t)(row + 8) * Kc + col) = __floats2half2_rn(a2, a3);
        }
    }

    #pragma unroll
    for (int mt = 0; mt < 4; mt++) {
        #pragma unroll
        for (int off = 1; off < 4; off <<= 1) {
            rmA[mt] = fmaxf(rmA[mt], __shfl_xor_sync(0xffffffffu, rmA[mt], off));
            rmB[mt] = fmaxf(rmB[mt], __shfl_xor_sync(0xffffffffu, rmB[mt], off));
        }
        if ((lane & 3) == 0) {
            int lr = wm * 64 + mt * 16 + (lane >> 2);
            smax[lr][wn]     = rmA[mt];
            smax[lr + 8][wn] = rmB[mt];
        }
    }
    __syncthreads();
    if (tid < 128) {
        float m = fmaxf(fmaxf(smax[tid][0], smax[tid][1]), fmaxf(smax[tid][2], smax[tid][3]));
        g_tmax[(size_t)(m0 + tid) * NTILES + blockIdx.x] = m;
    }
}

// ---------------- bf16 GEMM (general fallback, K=512) ----------------
__device__ __forceinline__ void load_stage_bf(uint32_t sbase, int st, int m0, int n0, int k0, int tid) {
    uint32_t ab = sbase + st * STAGE_BYTES;
    uint32_t bb = ab + 128 * ROWB;
    #pragma unroll
    for (int i = 0; i < 2; i++) {
        int lin = tid + (i << 8);
        int row = lin >> 2, ch = lin & 3;
        cp_async16(ab + row * ROWB + ch * 16, g_xb + (size_t)(m0 + row) * TWOD + k0 + ch * 8);
        cp_async16(bb + row * ROWB + ch * 16, g_wb + (size_t)(n0 + row) * TWOD + k0 + ch * 8);
    }
    CP_COMMIT();
}

__global__ void __launch_bounds__(256, 2) gemm_bf16_kernel() {
    if (g_flag) return;
    extern __shared__ char smem[];
    __shared__ float smax[128][4];
    uint32_t sbase = smem_u32(smem);
    int tid = threadIdx.x, wid = tid >> 5, lane = tid & 31;
    int m0 = blockIdx.y * 128;
    int n0 = blockIdx.x * 128;
    int wm = wid >> 2, wn = wid & 3;

    float acc[4][4][4];
    #pragma unroll
    for (int mt = 0; mt < 4; mt++)
        #pragma unroll
        for (int nt = 0; nt < 4; nt++)
            #pragma unroll
            for (int q = 0; q < 4; q++) acc[mt][nt][q] = 0.0f;

    load_stage_bf(sbase, 0, m0, n0, 0, tid);
    load_stage_bf(sbase, 1, m0, n0, 32, tid);
    load_stage_bf(sbase, 2, m0, n0, 64, tid);

    uint32_t a_row = (uint32_t)(wm * 64 + (lane & 15));
    uint32_t a_off = a_row * ROWB + ((lane >> 4) << 4);
    uint32_t b_row = (uint32_t)(wn * 32 + (lane & 7) + ((lane >> 4) << 3));
    uint32_t b_off = b_row * ROWB + (((lane >> 3) & 1) << 4);

    #pragma unroll 1
    for (int it = 0; it < 16; it++) {
        CP_WAIT(2);
        __syncthreads();
        if (it + 3 < 16) load_stage_bf(sbase, (it + 3) % NSTAGE, m0, n0, (it + 3) * 32, tid);
        else CP_COMMIT();

        int st = it % NSTAGE;
        uint32_t ab = sbase + st * STAGE_BYTES;
        uint32_t bb = ab + 128 * ROWB;

        #pragma unroll
        for (int ks = 0; ks < 2; ks++) {
            uint32_t afr[4][4];
            #pragma unroll
            for (int mt = 0; mt < 4; mt++)
                LDSM_X4(afr[mt], ab + a_off + mt * (16 * ROWB) + ks * 32);
            uint32_t bfr[2][4];
            #pragma unroll
            for (int np = 0; np < 2; np++)
                LDSM_X4(bfr[np], bb + b_off + np * (16 * ROWB) + ks * 32);
            #pragma unroll
            for (int mt = 0; mt < 4; mt++)
                #pragma unroll
                for (int nt = 0; nt < 4; nt++)
                    mma16816(acc[mt][nt], afr[mt],
                             bfr[nt >> 1][(nt & 1) * 2], bfr[nt >> 1][(nt & 1) * 2 + 1]);
        }
    }
    CP_WAIT(0);

    const float NI = neg_inf();
    float rmA[4], rmB[4];
    #pragma unroll
    for (int mt = 0; mt < 4; mt++) { rmA[mt] = NI; rmB[mt] = NI; }

    #pragma unroll
    for (int nt = 0; nt < 4; nt++) {
        int col = n0 + wn * 32 + nt * 8 + (lane & 3) * 2;
        float2 bb2 = *(const float2*)&g_bias[col];
        float bx = bb2.x + SHIFT_FULL, by = bb2.y + SHIFT_FULL;
        #pragma unroll
        for (int mt = 0; mt < 4; mt++) {
            int row = m0 + wm * 64 + mt * 16 + (lane >> 2);
            float a0 = acc[mt][nt][0] + bx, a1 = acc[mt][nt][1] + by;
            float a2 = acc[mt][nt][2] + bx, a3 = acc[mt][nt][3] + by;
            rmA[mt] = fmaxf(rmA[mt], fmaxf(a0, a1));
            rmB[mt] = fmaxf(rmB[mt], fmaxf(a2, a3));
            *(__half2*)(g_lh + (size_t)row * Kc + col)       = __floats2half2_rn(a0, a1);
            *(__half2*)(g_lh + (size_t)(row + 8) * Kc + col) = __floats2half2_rn(a2, a3);
        }
    }

    #pragma unroll
    for (int mt = 0; mt < 4; mt++) {
        #pragma unroll
        for (int off = 1; off < 4; off <<= 1) {
            rmA[mt] = fmaxf(rmA[mt], __shfl_xor_sync(0xffffffffu, rmA[mt], off));
            rmB[mt] = fmaxf(rmB[mt], __shfl_xor_sync(0xffffffffu, rmB[mt], off));
        }
        if ((lane & 3) == 0) {
            int lr = wm * 64 + mt * 16 + (lane >> 2);
            smax[lr][wn]     = rmA[mt];
            smax[lr + 8][wn] = rmB[mt];
        }
    }
    __syncthreads();
    if (tid < 128) {
        float m = fmaxf(fmaxf(smax[tid][0], smax[tid][1]), fmaxf(smax[tid][2], smax[tid][3]));
        g_tmax[(size_t)(m0 + tid) * NTILES + blockIdx.x] = m;
    }
}

// ---------------- topk: tile-max guided selection + exact rescore ----------------
__global__ void __launch_bounds__(512) topk_kernel(const float* __restrict__ x,
                                                   const float* __restrict__ mean,
                                                   const float* __restrict__ stddev,
                                                   const float* __restrict__ outputs,
                                                   float* __restrict__ out) {
    int b = blockIdx.x, t = threadIdx.x;
    int lane = t & 31, warp = t >> 5;
    const float NI = neg_inf();
    int uni = g_flag;

    __shared__ int   s_tiles[TCAP];
    __shared__ int   s_nt, s_cnt;
    __shared__ int   sred[16];
    __shared__ uint32_t s_cand[NCAP];
    __shared__ float s_clp[NCAP];
    __shared__ float s_fv[TOPK];
    __shared__ int   s_fi[TOPK];
    __shared__ float s_w[TOPK];
    __shared__ float part[2 * 256];

    // ---- stage 1: tile-max threshold via block-vote binary search ----
    uint32_t tk = fkey(g_tmax[(size_t)b * NTILES + t]);
    uint32_t cur = 0;
    #pragma unroll 1
    for (int bit = 31; bit >= 0; --bit) {
        uint32_t T = cur | (1u << bit);
        int n = __syncthreads_count(tk >= T);
        if (n >= NCAND) cur = T;
    }
    if (t == 0) s_nt = 0;
    __syncthreads();
    if (tk >= cur) {
        int p = atomicAdd(&s_nt, 1);
        if (p < TCAP) s_tiles[p] = t;
    }
    __syncthreads();
    int ntl = s_nt < TCAP ? s_nt : TCAP;
    int total = ntl * 64;          // u32 words across selected tiles

    // ---- stage 2: gather selected tiles into registers as 16-bit keys ----
    const uint32_t* row32 = (const uint32_t*)(g_lh + (size_t)b * Kc);
    uint32_t u[16];
    #pragma unroll
    for (int i = 0; i < 16; i++) {
        int w = t + (i << 9);
        if (w < total) {
            int tile = s_tiles[w >> 6];
            u[i] = key2(row32[tile * 64 + (w & 63)]);
        } else {
            u[i] = 0x03FF03FFu;    // key of -inf in both halves
        }
    }

    // ---- stage 3: exact 16-bit threshold via block-sum binary search ----
    uint32_t cur16 = 0;
    #pragma unroll 1
    for (int bit = 15; bit >= 0; --bit) {
        uint32_t T = cur16 | (1u << bit);
        int c = 0;
        #pragma unroll
        for (int i = 0; i < 16; i++)
            c += ((u[i] & 0xFFFFu) >= T) + ((u[i] >> 16) >= T);
        #pragma unroll
        for (int off = 16; off > 0; off >>= 1)
            c += __shfl_xor_sync(0xffffffffu, c, off);
        __syncthreads();
        if (lane == 0) sred[warp] = c;
        __syncthreads();
        int n = 0;
        #pragma unroll
        for (int w = 0; w < 16; w++) n += sred[w];
        if (n >= NCAND) cur16 = T;
    }
    if (t == 0) s_cnt = 0;
    if (t < NCAP) s_clp[t] = NI;
    __syncthreads();

    // ---- stage 4: collect candidates ----
    #pragma unroll
    for (int i = 0; i < 16; i++) {
        int w = t + (i << 9);
        if (w < total) {
            uint32_t klo = u[i] & 0xFFFFu, khi = u[i] >> 16;
            uint32_t idx = (uint32_t)(s_tiles[w >> 6] * 128 + (w & 63) * 2);
            if (klo >= cur16) {
                int p = atomicAdd(&s_cnt, 1);
                if (p < NCAP) s_cand[p] = (klo << 16) | idx;
            }
            if (khi >= cur16) {
                int p = atomicAdd(&s_cnt, 1);
                if (p < NCAP) s_cand[p] = (khi << 16) | (idx + 1);
            }
        }
    }
    __syncthreads();
    int M = s_cnt < NCAP ? s_cnt : NCAP;

    // ---- exact fp32 rescore (one warp per candidate) ----
    for (int cc = warp; cc < M; cc += 16) {
        int c = (int)(s_cand[cc] & 0xFFFFu);
        float sq = 0.0f, sl = 0.0f;
        if (uni) {
            #pragma unroll
            for (int jj = 0; jj < 8; jj++) {
                int d = lane + (jj << 5);
                float m  = mean[(size_t)c * Dc + d];
                float xv = x[(size_t)b * Dc + d];
                float df = xv - m;
                sq = fmaf(df, df, sq);
            }
        } else {
            #pragma unroll
            for (int jj = 0; jj < 8; jj++) {
                int d = lane + (jj << 5);
                float m  = mean[(size_t)c * Dc + d];
                float sd = stddev[(size_t)c * Dc + d];
                float xv = x[(size_t)b * Dc + d];
                float iv = 1.0f / (sd * sd);
                float df = xv - m;
                sq = fmaf(df * df, iv, sq);
                sl += logf(sd);
            }
        }
        #pragma unroll
        for (int off = 16; off > 0; off >>= 1) {
            sq += __shfl_xor_sync(0xffffffffu, sq, off);
            sl += __shfl_xor_sync(0xffffffffu, sl, off);
        }
        if (lane == 0) s_clp[cc] = -0.5f * sq - sl - HALF_D_LOG2PI;
    }
    __syncthreads();

    // ---- exact top-32 of up to 96 rescored values (warp 0, 3 slots/lane) ----
    if (warp == 0) {
        float va[3]; int ia[3];
        #pragma unroll
        for (int q = 0; q < 3; q++) { ia[q] = lane + q * 32; va[q] = s_clp[ia[q]]; }
        for (int r = 0; r < TOPK; r++) {
            float m = va[0]; int mi = ia[0];
            if (va[1] > m) { m = va[1]; mi = ia[1]; }
            if (va[2] > m) { m = va[2]; mi = ia[2]; }
            float bm = m; int bi = mi;
            #pragma unroll
            for (int off = 16; off > 0; off >>= 1) {
                float ov = __shfl_down_sync(0xffffffffu, bm, off);
                int   oi = __shfl_down_sync(0xffffffffu, bi, off);
                if (ov > bm) { bm = ov; bi = oi; }
            }
            bm = __shfl_sync(0xffffffffu, bm, 0);
            bi = __shfl_sync(0xffffffffu, bi, 0);
            if (lane == 0) { s_fv[r] = bm; s_fi[r] = (int)(s_cand[bi] & 0xFFFFu); }
            #pragma unroll
            for (int q = 0; q < 3; q++) if (ia[q] == bi) va[q] = NI;
        }
    }
    __syncthreads();

    if (t < TOPK) {
        float e = expf(s_fv[t] - s_fv[0]);
        float s = e;
        #pragma unroll
        for (int off = 16; off > 0; off >>= 1)
            s += __shfl_xor_sync(0xffffffffu, s, off);
        s_w[t] = e / s;
    }
    __syncthreads();

    int o = t & 255, g = t >> 8;   // g in {0,1}
    float p = 0.0f;
    #pragma unroll
    for (int j = 0; j < 16; j++) {
        int jj = g * 16 + j;
        p = fmaf(s_w[jj], outputs[(size_t)s_fi[jj] * Oc + o], p);
    }
    part[g * 256 + o] = p;
    __syncthreads();
    if (t < 256)
        out[(size_t)b * Oc + t] = part[t] + part[256 + t];
}

// ---------------- launch ----------------
extern "C" void kernel_launch(void* const* d_in, const int* in_sizes, int n_in,
                              void* d_out, int out_size) {
    const float* x       = (const float*)d_in[0];
    const float* mean    = (const float*)d_in[1];
    const float* stddev  = (const float*)d_in[2];
    const float* outputs = (const float*)d_in[3];
    float* out = (float*)d_out;

    cudaFuncSetAttribute(gemm_i8_kernel,   cudaFuncAttributeMaxDynamicSharedMemorySize, GEMM_SMEM);
    cudaFuncSetAttribute(gemm_bf16_kernel, cudaFuncAttributeMaxDynamicSharedMemorySize, GEMM_SMEM);

    prep_x_kernel<<<Bc, Dc>>>(x);
    prep_w_kernel<<<Kc / 4, 256>>>(mean, stddev);
    prep_w_bf16_kernel<<<Kc / 2, 512>>>(mean, stddev);
    gemm_i8_kernel<<<dim3(Kc / 128, Bc / 128), 256, GEMM_SMEM>>>();
    gemm_bf16_kernel<<<dim3(Kc / 128, Bc / 128), 256, GEMM_SMEM>>>();
    topk_kernel<<<Bc, 512>>>(x, mean, stddev, outputs, out);
}

// round 10
// speedup vs baseline: 1.4579x; 1.4579x over previous
#include <cuda_runtime.h>
#include <cuda_bf16.h>
#include <cuda_fp16.h>
#include <math.h>
#include <stdint.h>

#define Kc 65536
#define Dc 256
#define Oc 256
#define Bc 1024
#define TOPK 32
#define NCAND 48
#define NCAP 96
#define NTILES 512
#define TCAP 128
#define TWOD 512
#define SHIFT_FULL 491.25f
#define SHIFT_UNI  363.25f
#define HALF_D_LOG2PI 235.2482645f   // 0.5 * 256 * ln(2*pi)

// ---------------- device scratch ----------------
__device__ __nv_bfloat16 g_xb[(size_t)Bc * TWOD];        // 1 MB  [x | -0.5x^2]
__device__ __nv_bfloat16 g_wb[(size_t)Kc * TWOD];        // 64 MB [m*iv | iv]
__device__ float         g_bias[Kc];
__device__ __half        g_lh[(size_t)Bc * Kc];          // 128 MB shifted logits
__device__ __half        g_tmax[(size_t)Bc * NTILES];    // 1 MB per-row per-tile max (fp16)
__device__ int           g_flag;                          // 1 => stddev == 1 everywhere

__device__ __forceinline__ float neg_inf() { return __int_as_float(0xff800000); }

__device__ __forceinline__ uint32_t smem_u32(const void* p) {
    uint32_t a;
    asm("{ .reg .u64 t; cvta.to.shared.u64 t, %1; cvt.u32.u64 %0, t; }" : "=r"(a) : "l"(p));
    return a;
}
__device__ __forceinline__ void cp_async16(uint32_t dst, const void* src) {
    asm volatile("cp.async.cg.shared.global [%0], [%1], 16;" :: "r"(dst), "l"(src));
}
#define CP_COMMIT() asm volatile("cp.async.commit_group;" ::: "memory")
#define CP_WAIT(n)  asm volatile("cp.async.wait_group %0;" :: "n"(n) : "memory")

#define LDSM_X4(r, addr) \
    asm volatile("ldmatrix.sync.aligned.m8n8.x4.shared.b16 {%0,%1,%2,%3}, [%4];" \
        : "=r"((r)[0]), "=r"((r)[1]), "=r"((r)[2]), "=r"((r)[3]) : "r"(addr))

__device__ __forceinline__ void mma16816(float* c, const uint32_t* a, uint32_t b0, uint32_t b1) {
    asm volatile("mma.sync.aligned.m16n8k16.row.col.f32.bf16.bf16.f32 "
        "{%0,%1,%2,%3}, {%4,%5,%6,%7}, {%8,%9}, {%0,%1,%2,%3};"
        : "+f"(c[0]), "+f"(c[1]), "+f"(c[2]), "+f"(c[3])
        : "r"(a[0]), "r"(a[1]), "r"(a[2]), "r"(a[3]), "r"(b0), "r"(b1));
}

// both halves of a half2 word -> order-preserving 16-bit keys
__device__ __forceinline__ uint32_t key2(uint32_t h2) {
    uint32_t s = h2 & 0x80008000u;
    uint32_t m = 0x80008000u | ((s >> 15) * 0x7FFFu);
    return h2 ^ m;
}
__device__ __forceinline__ uint32_t hkey(uint32_t h) {   // single fp16 bits -> 16-bit key
    return h ^ ((h & 0x8000u) ? 0xFFFFu : 0x8000u);
}

// ---------------- prep kernels ----------------
__global__ void prep_x_kernel(const float* __restrict__ x) {
    int b = blockIdx.x, d = threadIdx.x;
    float v = x[b * Dc + d];
    g_xb[(size_t)b * TWOD + d]      = __float2bfloat16(v);
    g_xb[(size_t)b * TWOD + Dc + d] = __float2bfloat16(-0.5f * v * v);
    if (b == 0 && d == 0) g_flag = 1;   // reset each launch (graph-replay safe)
}

// warp per k-row, lane handles 8 elements; writes only the m*iv half (32 MB)
__global__ void __launch_bounds__(256) prep_w_kernel(const float* __restrict__ mean,
                                                     const float* __restrict__ stddev) {
    int warp = threadIdx.x >> 5, lane = threadIdx.x & 31;
    int k = blockIdx.x * 8 + warp;
    int e = lane * 8;
    const float* mp = mean   + (size_t)k * Dc + e;
    const float* sp = stddev + (size_t)k * Dc + e;
    float4 ma = *(const float4*)mp,      mb = *(const float4*)(mp + 4);
    float4 sa = *(const float4*)sp,      sb = *(const float4*)(sp + 4);

    bool nonuni = (sa.x != 1.0f) | (sa.y != 1.0f) | (sa.z != 1.0f) | (sa.w != 1.0f) |
                  (sb.x != 1.0f) | (sb.y != 1.0f) | (sb.z != 1.0f) | (sb.w != 1.0f);
    if (nonuni) g_flag = 0;

    float m8[8] = {ma.x, ma.y, ma.z, ma.w, mb.x, mb.y, mb.z, mb.w};
    float s8[8] = {sa.x, sa.y, sa.z, sa.w, sb.x, sb.y, sb.z, sb.w};
    float part = 0.0f;
    __nv_bfloat16 w8[8];
    #pragma unroll
    for (int i = 0; i < 8; i++) {
        float iv = 1.0f / (s8[i] * s8[i]);
        float miv = m8[i] * iv;
        w8[i] = __float2bfloat16(miv);
        part = fmaf(-0.5f * m8[i], miv, part);
    }
    if (nonuni) {
        #pragma unroll
        for (int i = 0; i < 8; i++) part -= logf(s8[i]);
    }
    *(uint4*)&g_wb[(size_t)k * TWOD + e] = *(uint4*)w8;

    #pragma unroll
    for (int off = 16; off > 0; off >>= 1)
        part += __shfl_xor_sync(0xffffffffu, part, off);
    if (lane == 0) g_bias[k] = part - HALF_D_LOG2PI;
}

// fix-up: writes the iv half; runs only when some stddev != 1
__global__ void __launch_bounds__(256) prep_w_fix_kernel(const float* __restrict__ stddev) {
    if (g_flag) return;
    int warp = threadIdx.x >> 5, lane = threadIdx.x & 31;
    int k = blockIdx.x * 8 + warp;
    int e = lane * 8;
    const float* sp = stddev + (size_t)k * Dc + e;
    float4 sa = *(const float4*)sp, sb = *(const float4*)(sp + 4);
    float s8[8] = {sa.x, sa.y, sa.z, sa.w, sb.x, sb.y, sb.z, sb.w};
    __nv_bfloat16 w8[8];
    #pragma unroll
    for (int i = 0; i < 8; i++)
        w8[i] = __float2bfloat16(1.0f / (s8[i] * s8[i]));
    *(uint4*)&g_wb[(size_t)k * TWOD + Dc + e] = *(uint4*)w8;
}

// ---------------- mma.sync bf16 GEMM (+ per-tile row max) ----------------
#define NSTAGE 4
#define ROWB   80
#define STAGE_BYTES (128 * ROWB * 2)   // A + B per stage = 20480
#define GEMM_SMEM (NSTAGE * STAGE_BYTES)

__device__ __forceinline__ void load_stage(uint32_t sbase, int st, int m0, int n0, int k0, int tid) {
    uint32_t ab = sbase + st * STAGE_BYTES;
    uint32_t bb = ab + 128 * ROWB;
    #pragma unroll
    for (int i = 0; i < 2; i++) {
        int lin = tid + (i << 8);
        int row = lin >> 2, ch = lin & 3;
        cp_async16(ab + row * ROWB + ch * 16, g_xb + (size_t)(m0 + row) * TWOD + k0 + ch * 8);
        cp_async16(bb + row * ROWB + ch * 16, g_wb + (size_t)(n0 + row) * TWOD + k0 + ch * 8);
    }
    CP_COMMIT();
}

__global__ void __launch_bounds__(256, 2) gemm_kernel() {
    extern __shared__ char smem[];
    __shared__ float smax[128][4];
    uint32_t sbase = smem_u32(smem);
    int tid = threadIdx.x, wid = tid >> 5, lane = tid & 31;
    int m0 = blockIdx.y * 128;
    int n0 = blockIdx.x * 128;
    int wm = wid >> 2, wn = wid & 3;

    int uni = g_flag;
    int KT = uni ? 8 : 16;
    float SHIFTV = uni ? SHIFT_UNI : SHIFT_FULL;

    float acc[4][4][4];
    #pragma unroll
    for (int mt = 0; mt < 4; mt++)
        #pragma unroll
        for (int nt = 0; nt < 4; nt++)
            #pragma unroll
            for (int q = 0; q < 4; q++) acc[mt][nt][q] = 0.0f;

    load_stage(sbase, 0, m0, n0, 0, tid);
    load_stage(sbase, 1, m0, n0, 32, tid);
    load_stage(sbase, 2, m0, n0, 64, tid);

    uint32_t a_row = (uint32_t)(wm * 64 + (lane & 15));
    uint32_t a_off = a_row * ROWB + ((lane >> 4) << 4);
    uint32_t b_row = (uint32_t)(wn * 32 + (lane & 7) + ((lane >> 4) << 3));
    uint32_t b_off = b_row * ROWB + (((lane >> 3) & 1) << 4);

    #pragma unroll 1
    for (int it = 0; it < KT; it++) {
        CP_WAIT(2);
        __syncthreads();
        if (it + 3 < KT) load_stage(sbase, (it + 3) % NSTAGE, m0, n0, (it + 3) * 32, tid);
        else CP_COMMIT();

        int st = it % NSTAGE;
        uint32_t ab = sbase + st * STAGE_BYTES;
        uint32_t bb = ab + 128 * ROWB;

        #pragma unroll
        for (int ks = 0; ks < 2; ks++) {
            uint32_t afr[4][4];
            #pragma unroll
            for (int mt = 0; mt < 4; mt++)
                LDSM_X4(afr[mt], ab + a_off + mt * (16 * ROWB) + ks * 32);
            uint32_t bfr[2][4];
            #pragma unroll
            for (int np = 0; np < 2; np++)
                LDSM_X4(bfr[np], bb + b_off + np * (16 * ROWB) + ks * 32);
            #pragma unroll
            for (int mt = 0; mt < 4; mt++)
                #pragma unroll
                for (int nt = 0; nt < 4; nt++)
                    mma16816(acc[mt][nt], afr[mt],
                             bfr[nt >> 1][(nt & 1) * 2], bfr[nt >> 1][(nt & 1) * 2 + 1]);
        }
    }
    CP_WAIT(0);

    const float NI = neg_inf();
    float rmA[4], rmB[4];
    #pragma unroll
    for (int mt = 0; mt < 4; mt++) { rmA[mt] = NI; rmB[mt] = NI; }

    #pragma unroll
    for (int nt = 0; nt < 4; nt++) {
        int col = n0 + wn * 32 + nt * 8 + (lane & 3) * 2;
        float2 bb2 = *(const float2*)&g_bias[col];
        float bx = bb2.x + SHIFTV, by = bb2.y + SHIFTV;
        #pragma unroll
        for (int mt = 0; mt < 4; mt++) {
            int row = m0 + wm * 64 + mt * 16 + (lane >> 2);
            float a0 = acc[mt][nt][0] + bx, a1 = acc[mt][nt][1] + by;
            float a2 = acc[mt][nt][2] + bx, a3 = acc[mt][nt][3] + by;
            rmA[mt] = fmaxf(rmA[mt], fmaxf(a0, a1));
            rmB[mt] = fmaxf(rmB[mt], fmaxf(a2, a3));
            *(__half2*)(g_lh + (size_t)row * Kc + col)       = __floats2half2_rn(a0, a1);
            *(__half2*)(g_lh + (size_t)(row + 8) * Kc + col) = __floats2half2_rn(a2, a3);
        }
    }

    #pragma unroll
    for (int mt = 0; mt < 4; mt++) {
        #pragma unroll
        for (int off = 1; off < 4; off <<= 1) {
            rmA[mt] = fmaxf(rmA[mt], __shfl_xor_sync(0xffffffffu, rmA[mt], off));
            rmB[mt] = fmaxf(rmB[mt], __shfl_xor_sync(0xffffffffu, rmB[mt], off));
        }
        if ((lane & 3) == 0) {
            int lr = wm * 64 + mt * 16 + (lane >> 2);
            smax[lr][wn]     = rmA[mt];
            smax[lr + 8][wn] = rmB[mt];
        }
    }
    __syncthreads();
    if (tid < 128) {
        float m = fmaxf(fmaxf(smax[tid][0], smax[tid][1]), fmaxf(smax[tid][2], smax[tid][3]));
        // rn is monotonic: half(max fp32) == max(half(v)) over the tile
        g_tmax[(size_t)(m0 + tid) * NTILES + blockIdx.x] = __float2half(m);
    }
}

// ---------------- topk: tile-max guided selection + exact rescore ----------------
__global__ void __launch_bounds__(512) topk_kernel(const float* __restrict__ x,
                                                   const float* __restrict__ mean,
                                                   const float* __restrict__ stddev,
                                                   const float* __restrict__ outputs,
                                                   float* __restrict__ out) {
    int b = blockIdx.x, t = threadIdx.x;
    int lane = t & 31, warp = t >> 5;
    const float NI = neg_inf();
    int uni = g_flag;

    __shared__ int   s_tiles[TCAP];
    __shared__ int   s_nt, s_cnt;
    __shared__ int   sred[16];
    __shared__ uint32_t s_cand[NCAP];
    __shared__ float s_clp[NCAP];
    __shared__ float s_fv[TOPK];
    __shared__ int   s_fi[TOPK];
    __shared__ float s_w[TOPK];
    __shared__ float part[2 * 256];

    // ---- stage 1: tile-max threshold via block-vote binary search (16-bit keys) ----
    uint32_t tk = hkey((uint32_t)__half_as_ushort(g_tmax[(size_t)b * NTILES + t]));
    uint32_t cur = 0;
    #pragma unroll 1
    for (int bit = 15; bit >= 0; --bit) {
        uint32_t T = cur | (1u << bit);
        int n = __syncthreads_count(tk >= T);
        if (n >= NCAND) cur = T;
    }
    if (t == 0) s_nt = 0;
    __syncthreads();
    if (tk >= cur) {
        int p = atomicAdd(&s_nt, 1);
        if (p < TCAP) s_tiles[p] = t;
    }
    __syncthreads();
    int ntl = s_nt < TCAP ? s_nt : TCAP;
    int total = ntl * 64;          // u32 words across selected tiles

    // ---- stage 2: gather selected tiles into registers as 16-bit keys ----
    const uint32_t* row32 = (const uint32_t*)(g_lh + (size_t)b * Kc);
    uint32_t u[16];
    #pragma unroll
    for (int i = 0; i < 16; i++) {
        int w = t + (i << 9);
        if (w < total) {
            int tile = s_tiles[w >> 6];
            u[i] = key2(row32[tile * 64 + (w & 63)]);
        } else {
            u[i] = 0x03FF03FFu;    // key of -inf in both halves
        }
    }

    // ---- stage 3: exact 16-bit threshold via block-sum binary search ----
    uint32_t cur16 = 0;
    #pragma unroll 1
    for (int bit = 15; bit >= 0; --bit) {
        uint32_t T = cur16 | (1u << bit);
        int c = 0;
        #pragma unroll
        for (int i = 0; i < 16; i++)
            c += ((u[i] & 0xFFFFu) >= T) + ((u[i] >> 16) >= T);
        #pragma unroll
        for (int off = 16; off > 0; off >>= 1)
            c += __shfl_xor_sync(0xffffffffu, c, off);
        __syncthreads();
        if (lane == 0) sred[warp] = c;
        __syncthreads();
        int n = 0;
        #pragma unroll
        for (int w = 0; w < 16; w++) n += sred[w];
        if (n >= NCAND) cur16 = T;
    }
    if (t == 0) s_cnt = 0;
    if (t < NCAP) s_clp[t] = NI;
    __syncthreads();

    // ---- stage 4: collect candidates ----
    #pragma unroll
    for (int i = 0; i < 16; i++) {
        int w = t + (i << 9);
        if (w < total) {
            uint32_t klo = u[i] & 0xFFFFu, khi = u[i] >> 16;
            uint32_t idx = (uint32_t)(s_tiles[w >> 6] * 128 + (w & 63) * 2);
            if (klo >= cur16) {
                int p = atomicAdd(&s_cnt, 1);
                if (p < NCAP) s_cand[p] = (klo << 16) | idx;
            }
            if (khi >= cur16) {
                int p = atomicAdd(&s_cnt, 1);
                if (p < NCAP) s_cand[p] = (khi << 16) | (idx + 1);
            }
        }
    }
    __syncthreads();
    int M = s_cnt < NCAP ? s_cnt : NCAP;

    // ---- exact fp32 rescore (one warp per candidate) ----
    for (int cc = warp; cc < M; cc += 16) {
        int c = (int)(s_cand[cc] & 0xFFFFu);
        float sq = 0.0f, sl = 0.0f;
        if (uni) {
            #pragma unroll
            for (int jj = 0; jj < 8; jj++) {
                int d = lane + (jj << 5);
                float m  = mean[(size_t)c * Dc + d];
                float xv = x[(size_t)b * Dc + d];
                float df = xv - m;
                sq = fmaf(df, df, sq);
            }
        } else {
            #pragma unroll
            for (int jj = 0; jj < 8; jj++) {
                int d = lane + (jj << 5);
                float m  = mean[(size_t)c * Dc + d];
                float sd = stddev[(size_t)c * Dc + d];
                float xv = x[(size_t)b * Dc + d];
                float iv = 1.0f / (sd * sd);
                float df = xv - m;
                sq = fmaf(df * df, iv, sq);
                sl += logf(sd);
            }
        }
        #pragma unroll
        for (int off = 16; off > 0; off >>= 1) {
            sq += __shfl_xor_sync(0xffffffffu, sq, off);
            sl += __shfl_xor_sync(0xffffffffu, sl, off);
        }
        if (lane == 0) s_clp[cc] = -0.5f * sq - sl - HALF_D_LOG2PI;
    }
    __syncthreads();

    // ---- exact top-32 of up to 96 rescored values (warp 0, 3 slots/lane) ----
    if (warp == 0) {
        float va[3]; int ia[3];
        #pragma unroll
        for (int q = 0; q < 3; q++) { ia[q] = lane + q * 32; va[q] = s_clp[ia[q]]; }
        for (int r = 0; r < TOPK; r++) {
            float m = va[0]; int mi = ia[0];
            if (va[1] > m) { m = va[1]; mi = ia[1]; }
            if (va[2] > m) { m = va[2]; mi = ia[2]; }
            float bm = m; int bi = mi;
            #pragma unroll
            for (int off = 16; off > 0; off >>= 1) {
                float ov = __shfl_down_sync(0xffffffffu, bm, off);
                int   oi = __shfl_down_sync(0xffffffffu, bi, off);
                if (ov > bm) { bm = ov; bi = oi; }
            }
            bm = __shfl_sync(0xffffffffu, bm, 0);
            bi = __shfl_sync(0xffffffffu, bi, 0);
            if (lane == 0) { s_fv[r] = bm; s_fi[r] = (int)(s_cand[bi] & 0xFFFFu); }
            #pragma unroll
            for (int q = 0; q < 3; q++) if (ia[q] == bi) va[q] = NI;
        }
    }
    __syncthreads();

    if (t < TOPK) {
        float e = expf(s_fv[t] - s_fv[0]);
        float s = e;
        #pragma unroll
        for (int off = 16; off > 0; off >>= 1)
            s += __shfl_xor_sync(0xffffffffu, s, off);
        s_w[t] = e / s;
    }
    __syncthreads();

    int o = t & 255, g = t >> 8;   // g in {0,1}
    float p = 0.0f;
    #pragma unroll
    for (int j = 0; j < 16; j++) {
        int jj = g * 16 + j;
        p = fmaf(s_w[jj], outputs[(size_t)s_fi[jj] * Oc + o], p);
    }
    part[g * 256 + o] = p;
    __syncthreads();
    if (t < 256)
        out[(size_t)b * Oc + t] = part[t] + part[256 + t];
}

// ---------------- launch ----------------
extern "C" void kernel_launch(void* const* d_in, const int* in_sizes, int n_in,
                              void* d_out, int out_size) {
    const float* x       = (const float*)d_in[0];
    const float* mean    = (const float*)d_in[1];
    const float* stddev  = (const float*)d_in[2];
    const float* outputs = (const float*)d_in[3];
    float* out = (float*)d_out;

    cudaFuncSetAttribute(gemm_kernel, cudaFuncAttributeMaxDynamicSharedMemorySize, GEMM_SMEM);

    prep_x_kernel<<<Bc, Dc>>>(x);
    prep_w_kernel<<<Kc / 8, 256>>>(mean, stddev);
    prep_w_fix_kernel<<<Kc / 8, 256>>>(stddev);
    gemm_kernel<<<dim3(Kc / 128, Bc / 128), 256, GEMM_SMEM>>>();
    topk_kernel<<<Bc, 512>>>(x, mean, stddev, outputs, out);
}